// round 17
// baseline (speedup 1.0000x reference)
#include <cuda_runtime.h>
#include <cuda_fp16.h>
#include <cstdint>
#include <math.h>

#define BDIM 2
#define TSEQ 2048
#define DMODEL 1024
#define DM32 (DMODEL / 2)     // row stride in u32 (packed half2)
#define NHEADS 16
#define DK 64
#define MTOK (BDIM * TSEQ)    // 4096

// -------- scratch (device globals; packed fp16 pairs as u32) --------
__device__ uint32_t g_xh[MTOK * DM32];
__device__ uint32_t g_Wh[4 * DMODEL * DM32];
__device__ uint32_t g_Q[MTOK * DM32];
__device__ uint32_t g_K[MTOK * DM32];
__device__ uint32_t g_V[MTOK * DM32];
__device__ uint32_t g_ctx[MTOK * DM32];

// ============================================================================
// helpers
// ============================================================================
__device__ __forceinline__ uint32_t smem_u32(const void* p) {
    uint32_t a;
    asm("{ .reg .u64 t; cvta.to.shared.u64 t, %1; cvt.u32.u64 %0, t; }" : "=r"(a) : "l"(p));
    return a;
}

__device__ __forceinline__ uint32_t pack_h2(float lo, float hi) {
    uint32_t r;
    asm("cvt.rn.f16x2.f32 %0, %1, %2;" : "=r"(r) : "f"(hi), "f"(lo));
    return r;
}

__device__ __forceinline__ void mma_f16(float* d, const uint32_t* a,
                                        uint32_t b0, uint32_t b1) {
    asm volatile(
        "mma.sync.aligned.m16n8k16.row.col.f32.f16.f16.f32 "
        "{%0,%1,%2,%3}, {%4,%5,%6,%7}, {%8,%9}, {%0,%1,%2,%3};"
        : "+f"(d[0]), "+f"(d[1]), "+f"(d[2]), "+f"(d[3])
        : "r"(a[0]), "r"(a[1]), "r"(a[2]), "r"(a[3]), "r"(b0), "r"(b1));
}

#define LDSM4(r0, r1, r2, r3, addr) \
    asm volatile("ldmatrix.sync.aligned.m8n8.x4.shared.b16 {%0,%1,%2,%3}, [%4];" \
                 : "=r"(r0), "=r"(r1), "=r"(r2), "=r"(r3) : "r"(addr))

#define CP_ASYNC16(dst, src) \
    asm volatile("cp.async.cg.shared.global [%0], [%1], 16;" \
                 :: "r"((uint32_t)(dst)), "l"(src) : "memory")
#define CP_COMMIT() asm volatile("cp.async.commit_group;" ::: "memory")
#define CP_WAIT1()  asm volatile("cp.async.wait_group 1;" ::: "memory")
#define CP_WAIT0()  asm volatile("cp.async.wait_group 0;" ::: "memory")

// ============================================================================
// Pre-convert fp32 -> packed fp16
// ============================================================================
#define XN4   (MTOK * DMODEL / 4)        // 1048576
#define WN4   (DMODEL * DMODEL / 4)      // 262144

__global__ __launch_bounds__(256)
void cvt_h_kernel(const float4* __restrict__ x,
                  const float4* __restrict__ wq, const float4* __restrict__ wk,
                  const float4* __restrict__ wv, const float4* __restrict__ wo,
                  uint2* __restrict__ xh, uint2* __restrict__ wh)
{
    const int i = blockIdx.x * 256 + threadIdx.x;
    const float4* src;
    uint2* dst;
    if (i < XN4) {
        src = x + i; dst = xh + i;
    } else {
        const int j = i - XN4;
        const int w = j >> 18;
        const int off = j & (WN4 - 1);
        const float4* ws[4] = { wq, wk, wv, wo };
        src = ws[w] + off;
        dst = wh + (size_t)w * WN4 + off;
    }
    float4 v = *src;
    uint2 u;
    u.x = pack_h2(v.x, v.y);
    u.y = pack_h2(v.z, v.w);
    *dst = u;
}

// ============================================================================
// fp16 mma.sync GEMM, ldmatrix loads, 3 CTAs/SM (reg cap 85).
// CTA 128x128, BK=64 halves, 256 thr (8 warps 4x2), warp tile 32x64.
// ============================================================================
#define NCHUNK 16
#define SR32 36
#define TILE_U (128 * SR32)
#define GEMM_SMEM (4 * TILE_U * 4)   // 73728 bytes

template<int STORE_HALF>
__global__ __launch_bounds__(256, 3)
void gemm_h_kernel(const uint32_t* __restrict__ A,
                   const uint32_t* __restrict__ W0, const uint32_t* __restrict__ W1,
                   const uint32_t* __restrict__ W2,
                   const float* __restrict__ b0, const float* __restrict__ b1,
                   const float* __restrict__ b2,
                   void* __restrict__ Y0, void* __restrict__ Y1,
                   void* __restrict__ Y2,
                   float s0, float s1, float s2)
{
    extern __shared__ uint32_t smem[];
    uint32_t* As0 = smem;
    uint32_t* Ws0 = As0 + TILE_U;
    uint32_t* As1 = Ws0 + TILE_U;
    uint32_t* Ws1 = As1 + TILE_U;

    const uint32_t* W = W0; const float* bias = b0; void* Y = Y0; float scale = s0;
    if (blockIdx.z == 1) { W = W1; bias = b1; Y = Y1; scale = s1; }
    else if (blockIdx.z == 2) { W = W2; bias = b2; Y = Y2; scale = s2; }

    const int tid  = threadIdx.x;
    const int wid  = tid >> 5;
    const int lane = tid & 31;
    const int m0 = blockIdx.y * 128;
    const int n0 = blockIdx.x * 128;

    const int m_warp = (wid & 3) * 32;
    const int n_warp = (wid >> 2) * 64;
    const int c4 = lane & 3;
    const int g8 = lane >> 2;

    const uint32_t aL = (uint32_t)((m_warp + (lane & 15)) * SR32 + (lane >> 4) * 4);
    const uint32_t bL = (uint32_t)((n_warp + ((lane >> 4) << 3) + (lane & 7)) * SR32
                                   + ((lane >> 3) & 1) * 4);

    const uint32_t sA0 = smem_u32(As0), sW0 = smem_u32(Ws0);
    const uint32_t sA1 = smem_u32(As1), sW1 = smem_u32(Ws1);

    const int rowL = tid >> 1;
    const int hof  = (tid & 1) * 16;
    const uint32_t* Abase = A + (size_t)(m0 + rowL) * DM32 + hof;
    const uint32_t* Wbase = W + (size_t)(n0 + rowL) * DM32 + hof;
    const uint32_t soff = (uint32_t)(rowL * SR32 + hof) * 4u;

#define LOAD_CHUNK(c) do {                                                    \
    uint32_t _da = (((c) & 1) ? sA1 : sA0) + soff;                            \
    uint32_t _dw = (((c) & 1) ? sW1 : sW0) + soff;                            \
    const uint32_t* _ga = Abase + (c) * 32;                                   \
    const uint32_t* _gw = Wbase + (c) * 32;                                   \
    CP_ASYNC16(_da,      _ga);      CP_ASYNC16(_da + 16, _ga + 4);            \
    CP_ASYNC16(_da + 32, _ga + 8);  CP_ASYNC16(_da + 48, _ga + 12);           \
    CP_ASYNC16(_dw,      _gw);      CP_ASYNC16(_dw + 16, _gw + 4);            \
    CP_ASYNC16(_dw + 32, _gw + 8);  CP_ASYNC16(_dw + 48, _gw + 12);           \
    CP_COMMIT();                                                              \
} while (0)

    float acc[2][8][4];
#pragma unroll
    for (int i = 0; i < 2; ++i)
#pragma unroll
        for (int j = 0; j < 8; ++j)
#pragma unroll
            for (int r = 0; r < 4; ++r) acc[i][j][r] = 0.f;

    LOAD_CHUNK(0);
    LOAD_CHUNK(1);

#pragma unroll 1
    for (int c = 0; c < NCHUNK; ++c) {
        if (c + 1 < NCHUNK) CP_WAIT1(); else CP_WAIT0();
        __syncthreads();

        const uint32_t aBuf = ((c & 1) ? sA1 : sA0) + aL * 4u;
        const uint32_t bBuf = ((c & 1) ? sW1 : sW0) + bL * 4u;

#pragma unroll
        for (int ks = 0; ks < 4; ++ks) {
            uint32_t a[2][4];
            LDSM4(a[0][0], a[0][1], a[0][2], a[0][3], aBuf + ks * 32u);
            LDSM4(a[1][0], a[1][1], a[1][2], a[1][3],
                  aBuf + 16u * SR32 * 4u + ks * 32u);
#pragma unroll
            for (int ntp = 0; ntp < 4; ++ntp) {
                uint32_t b[4];
                LDSM4(b[0], b[1], b[2], b[3],
                      bBuf + (uint32_t)(ntp * 16 * SR32) * 4u + ks * 32u);
                mma_f16(acc[0][2 * ntp],     a[0], b[0], b[1]);
                mma_f16(acc[1][2 * ntp],     a[1], b[0], b[1]);
                mma_f16(acc[0][2 * ntp + 1], a[0], b[2], b[3]);
                mma_f16(acc[1][2 * ntp + 1], a[1], b[2], b[3]);
            }
        }

        __syncthreads();
        if (c + 2 < NCHUNK) LOAD_CHUNK(c + 2);
    }
#undef LOAD_CHUNK

#pragma unroll
    for (int mt = 0; mt < 2; ++mt) {
        const int row = m0 + m_warp + mt * 16 + g8;
#pragma unroll
        for (int nt = 0; nt < 8; ++nt) {
            const int col = n0 + n_warp + nt * 8 + c4 * 2;
            const float bx = bias[col], by = bias[col + 1];
            if (STORE_HALF) {
                uint32_t* y0 = (uint32_t*)Y + (size_t)row * DM32 + col / 2;
                uint32_t* y1 = (uint32_t*)Y + (size_t)(row + 8) * DM32 + col / 2;
                *y0 = pack_h2((acc[mt][nt][0] + bx) * scale,
                              (acc[mt][nt][1] + by) * scale);
                *y1 = pack_h2((acc[mt][nt][2] + bx) * scale,
                              (acc[mt][nt][3] + by) * scale);
            } else {
                float* y0 = (float*)Y + (size_t)row * DMODEL + col;
                float* y1 = (float*)Y + (size_t)(row + 8) * DMODEL + col;
                *(float2*)y0 = make_float2(acc[mt][nt][0] + bx, acc[mt][nt][1] + by);
                *(float2*)y1 = make_float2(acc[mt][nt][2] + bx, acc[mt][nt][3] + by);
            }
        }
    }
}

// ============================================================================
// fp16 tensor-core causal flash attention, Bk=64 keys/tile.
// 8 warps x 16 q-rows; K smem u32[64][36]; Vt smem u32[64][36] (transposed).
// Softmax/sync overhead amortized over 64 keys; exp computed in place over s.
// ============================================================================
#define KST 36
#define VST 36

__global__ __launch_bounds__(256, 2)
void attn_h_kernel(const uint32_t* __restrict__ Q, const uint32_t* __restrict__ K,
                   const uint32_t* __restrict__ V, uint32_t* __restrict__ ctx)
{
    __shared__ uint32_t sK[2][64 * KST];
    __shared__ uint32_t sV[2][64 * VST];

    const int tid  = threadIdx.x;
    const int wid  = tid >> 5;
    const int lane = tid & 31;
    const int g8 = lane >> 2;
    const int c4 = lane & 3;

    const int bq = blockIdx.x;
    const int h  = blockIdx.y;
    const int b  = blockIdx.z;
    const int wq0 = bq * 128 + wid * 16;
    const size_t base32 = ((size_t)b * TSEQ) * DM32 + (size_t)h * (DK / 2);

    // B-operand ldmatrix lane base (u32)
    const uint32_t kL = (uint32_t)((((lane >> 4) << 3) + (lane & 7)) * KST
                                   + ((lane >> 3) & 1) * 4);
    const uint32_t vL = (uint32_t)((((lane >> 4) << 3) + (lane & 7)) * VST
                                   + ((lane >> 3) & 1) * 4);
    const uint32_t sKb[2] = { smem_u32(sK[0]) + kL * 4u, smem_u32(sK[1]) + kL * 4u };
    const uint32_t sVb[2] = { smem_u32(sV[0]) + vL * 4u, smem_u32(sV[1]) + vL * 4u };

    // ---- Q fragments ----
    uint32_t qa[4][4];
    {
        const uint32_t* qlo = Q + base32 + (size_t)(wq0 + g8) * DM32;
        const uint32_t* qhi = qlo + 8 * DM32;
#pragma unroll
        for (int ks = 0; ks < 4; ++ks) {
            qa[ks][0] = qlo[8 * ks + c4];
            qa[ks][1] = qhi[8 * ks + c4];
            qa[ks][2] = qlo[8 * ks + c4 + 4];
            qa[ks][3] = qhi[8 * ks + c4 + 4];
        }
    }

    const int ntiles = 2 * bq + 2;        // Bk=64 tiles to cover bq*128+128 keys

    // loader mappings
    const int kkey = tid >> 2, kx = (tid & 3) * 8;   // K: row 0..63, 8-u32 seg
    const int vkp  = tid & 31, vds = tid >> 5;       // V: key-pair 0..31, 4-u32 d-seg
    const uint32_t ka0 = smem_u32(sK[0]) + (uint32_t)(kkey * KST + kx) * 4u;
    const uint32_t ka1 = smem_u32(sK[1]) + (uint32_t)(kkey * KST + kx) * 4u;

#define STORE_VT(bufidx, u0, u1) do {                                         \
    uint32_t* Vn = sV[bufidx] + vkp;                                          \
    Vn[(8 * vds + 0) * VST] = __byte_perm((u0).x, (u1).x, 0x5410);            \
    Vn[(8 * vds + 1) * VST] = __byte_perm((u0).x, (u1).x, 0x7632);            \
    Vn[(8 * vds + 2) * VST] = __byte_perm((u0).y, (u1).y, 0x5410);            \
    Vn[(8 * vds + 3) * VST] = __byte_perm((u0).y, (u1).y, 0x7632);            \
    Vn[(8 * vds + 4) * VST] = __byte_perm((u0).z, (u1).z, 0x5410);            \
    Vn[(8 * vds + 5) * VST] = __byte_perm((u0).z, (u1).z, 0x7632);            \
    Vn[(8 * vds + 6) * VST] = __byte_perm((u0).w, (u1).w, 0x5410);            \
    Vn[(8 * vds + 7) * VST] = __byte_perm((u0).w, (u1).w, 0x7632);            \
} while (0)

    // ---- prologue: tile0 K + V; prefetch tile1 ----
    {
        const uint32_t* kr = K + base32 + (size_t)kkey * DM32 + kx;
        CP_ASYNC16(ka0, kr); CP_ASYNC16(ka0 + 16, kr + 4);
        CP_COMMIT();
    }
    {
        const uint32_t* v0 = V + base32 + (size_t)(2 * vkp) * DM32 + 4 * vds;
        uint4 u0 = *(const uint4*)v0, u1 = *(const uint4*)(v0 + DM32);
        STORE_VT(0, u0, u1);
    }
    uint4 va, vb;
    {
        const uint32_t* kr = K + base32 + (size_t)(64 + kkey) * DM32 + kx;
        CP_ASYNC16(ka1, kr); CP_ASYNC16(ka1 + 16, kr + 4);
        CP_COMMIT();
        const uint32_t* v0 = V + base32 + (size_t)(64 + 2 * vkp) * DM32 + 4 * vds;
        va = *(const uint4*)v0; vb = *(const uint4*)(v0 + DM32);
    }
    CP_WAIT1();
    __syncthreads();

    float m0 = -1e30f, m1 = -1e30f, l0 = 0.f, l1 = 0.f;
    float o[8][4];
#pragma unroll
    for (int nf = 0; nf < 8; ++nf)
#pragma unroll
        for (int r = 0; r < 4; ++r) o[nf][r] = 0.f;

    const int rlo = wq0 + g8, rhi = rlo + 8;

#pragma unroll 1
    for (int it = 0; it < ntiles; ++it) {
        const int k0 = it * 64;
        const uint32_t kBuf = sKb[it & 1];
        const uint32_t vBuf = sVb[it & 1];

        uint4 na, nb;
        const bool have2 = (it + 2 < ntiles);
        if (have2) {
            const uint32_t* v0 = V + base32
                + (size_t)((it + 2) * 64 + 2 * vkp) * DM32 + 4 * vds;
            na = *(const uint4*)v0; nb = *(const uint4*)(v0 + DM32);
        }

        if (k0 <= wq0 + 15) {
            // ---- S = Q K^T : 8 n-frags over 64 keys ----
            float s[8][4];
#pragma unroll
            for (int nf = 0; nf < 8; ++nf)
#pragma unroll
                for (int r = 0; r < 4; ++r) s[nf][r] = 0.f;
#pragma unroll
            for (int ks = 0; ks < 4; ++ks) {
#pragma unroll
                for (int nfp = 0; nfp < 4; ++nfp) {
                    uint32_t bfr[4];
                    LDSM4(bfr[0], bfr[1], bfr[2], bfr[3],
                          kBuf + (uint32_t)(nfp * 16 * KST) * 4u + ks * 32u);
                    mma_f16(s[2 * nfp],     qa[ks], bfr[0], bfr[1]);
                    mma_f16(s[2 * nfp + 1], qa[ks], bfr[2], bfr[3]);
                }
            }

            // ---- causal mask (diagonal tiles only) ----
            if (k0 + 63 > wq0) {
#pragma unroll
                for (int nf = 0; nf < 8; ++nf) {
                    const int kg = k0 + nf * 8 + 2 * c4;
                    if (kg     > rlo) s[nf][0] = -1e30f;
                    if (kg + 1 > rlo) s[nf][1] = -1e30f;
                    if (kg     > rhi) s[nf][2] = -1e30f;
                    if (kg + 1 > rhi) s[nf][3] = -1e30f;
                }
            }

            // ---- online softmax (exp in place over s) ----
            float tl = -1e30f, th = -1e30f;
#pragma unroll
            for (int nf = 0; nf < 8; ++nf) {
                tl = fmaxf(tl, fmaxf(s[nf][0], s[nf][1]));
                th = fmaxf(th, fmaxf(s[nf][2], s[nf][3]));
            }
            tl = fmaxf(tl, __shfl_xor_sync(0xffffffffu, tl, 1));
            tl = fmaxf(tl, __shfl_xor_sync(0xffffffffu, tl, 2));
            th = fmaxf(th, __shfl_xor_sync(0xffffffffu, th, 1));
            th = fmaxf(th, __shfl_xor_sync(0xffffffffu, th, 2));

            const float mn0 = fmaxf(m0, tl), mn1 = fmaxf(m1, th);
            const float cr0 = __expf(m0 - mn0), cr1 = __expf(m1 - mn1);
            float sl = 0.f, sh = 0.f;
#pragma unroll
            for (int nf = 0; nf < 8; ++nf) {
                s[nf][0] = __expf(s[nf][0] - mn0);
                s[nf][1] = __expf(s[nf][1] - mn0);
                s[nf][2] = __expf(s[nf][2] - mn1);
                s[nf][3] = __expf(s[nf][3] - mn1);
                sl += s[nf][0] + s[nf][1];
                sh += s[nf][2] + s[nf][3];
            }
            sl += __shfl_xor_sync(0xffffffffu, sl, 1);
            sl += __shfl_xor_sync(0xffffffffu, sl, 2);
            sh += __shfl_xor_sync(0xffffffffu, sh, 1);
            sh += __shfl_xor_sync(0xffffffffu, sh, 2);
            l0 = l0 * cr0 + sl;  l1 = l1 * cr1 + sh;
            m0 = mn0;  m1 = mn1;
#pragma unroll
            for (int nf = 0; nf < 8; ++nf) {
                o[nf][0] *= cr0; o[nf][1] *= cr0;
                o[nf][2] *= cr1; o[nf][3] *= cr1;
            }

            // ---- O += P V : 4 k16 steps over 64 keys ----
#pragma unroll
            for (int ks = 0; ks < 4; ++ks) {
                uint32_t a[4];
                a[0] = pack_h2(s[2 * ks][0],     s[2 * ks][1]);
                a[1] = pack_h2(s[2 * ks][2],     s[2 * ks][3]);
                a[2] = pack_h2(s[2 * ks + 1][0], s[2 * ks + 1][1]);
                a[3] = pack_h2(s[2 * ks + 1][2], s[2 * ks + 1][3]);
#pragma unroll
                for (int nfp = 0; nfp < 4; ++nfp) {
                    uint32_t bfr[4];
                    LDSM4(bfr[0], bfr[1], bfr[2], bfr[3],
                          vBuf + (uint32_t)(nfp * 16 * VST) * 4u + ks * 32u);
                    mma_f16(o[2 * nfp],     a, bfr[0], bfr[1]);
                    mma_f16(o[2 * nfp + 1], a, bfr[2], bfr[3]);
                }
            }
        }

        // ---- pipeline advance ----
        if (it + 1 < ntiles) {
            CP_WAIT0();
            __syncthreads();
            STORE_VT((it + 1) & 1, va, vb);
            if (have2) {
                const uint32_t* kr = K + base32
                    + (size_t)((it + 2) * 64 + kkey) * DM32 + kx;
                const uint32_t dst = (it & 1) ? ka1 : ka0;
                CP_ASYNC16(dst, kr); CP_ASYNC16(dst + 16, kr + 4);
                CP_COMMIT();
                va = na; vb = nb;
            }
            __syncthreads();
        }
    }
#undef STORE_VT

    // ---- epilogue: ctx as packed fp16 ----
    const float inv0 = 1.f / l0, inv1 = 1.f / l1;
    uint32_t* olo = ctx + base32 + (size_t)rlo * DM32;
    uint32_t* ohi = ctx + base32 + (size_t)rhi * DM32;
#pragma unroll
    for (int nf = 0; nf < 8; ++nf) {
        olo[nf * 4 + c4] = pack_h2(o[nf][0] * inv0, o[nf][1] * inv0);
        ohi[nf * 4 + c4] = pack_h2(o[nf][2] * inv1, o[nf][3] * inv1);
    }
}

// ============================================================================
// launch
// ============================================================================
extern "C" void kernel_launch(void* const* d_in, const int* in_sizes, int n_in,
                              void* d_out, int out_size)
{
    const float* x  = (const float*)d_in[0];
    const float* Wq = (const float*)d_in[1];
    const float* bq = (const float*)d_in[2];
    const float* Wk = (const float*)d_in[3];
    const float* bk = (const float*)d_in[4];
    const float* Wv = (const float*)d_in[5];
    const float* bv = (const float*)d_in[6];
    const float* Wo = (const float*)d_in[7];
    const float* bo = (const float*)d_in[8];
    float* out = (float*)d_out;

    uint32_t *xh, *wh, *qp, *kp, *vp, *cp;
    cudaGetSymbolAddress((void**)&xh, g_xh);
    cudaGetSymbolAddress((void**)&wh, g_Wh);
    cudaGetSymbolAddress((void**)&qp, g_Q);
    cudaGetSymbolAddress((void**)&kp, g_K);
    cudaGetSymbolAddress((void**)&vp, g_V);
    cudaGetSymbolAddress((void**)&cp, g_ctx);

    cudaFuncSetAttribute(gemm_h_kernel<1>,
                         cudaFuncAttributeMaxDynamicSharedMemorySize, GEMM_SMEM);
    cudaFuncSetAttribute(gemm_h_kernel<0>,
                         cudaFuncAttributeMaxDynamicSharedMemorySize, GEMM_SMEM);

    // 1) pre-convert x + weights to packed fp16
    cvt_h_kernel<<<(XN4 + 4 * WN4) / 256, 256>>>(
        (const float4*)x, (const float4*)Wq, (const float4*)Wk,
        (const float4*)Wv, (const float4*)Wo, (uint2*)xh, (uint2*)wh);

    // 2) fused QKV projections (Q scaled by 1/sqrt(dk))
    const size_t W32 = (size_t)DMODEL * DM32;
    dim3 qkv_grid(DMODEL / 128, MTOK / 128, 3);
    gemm_h_kernel<1><<<qkv_grid, 256, GEMM_SMEM>>>(
        xh, wh, wh + W32, wh + 2 * W32,
        bq, bk, bv, qp, kp, vp, 0.125f, 1.f, 1.f);

    // 3) attention
    dim3 agrid(TSEQ / 128, NHEADS, BDIM);
    attn_h_kernel<<<agrid, 256>>>(qp, kp, vp, cp);

    // 4) output projection -> fp32 d_out
    dim3 o_grid(DMODEL / 128, MTOK / 128, 1);
    gemm_h_kernel<0><<<o_grid, 256, GEMM_SMEM>>>(
        cp, wh + 3 * W32, wh, wh,
        bo, bo, bo, out, out, out, 1.f, 1.f, 1.f);
}